// round 14
// baseline (speedup 1.0000x reference)
#include <cuda_runtime.h>

#define H 512
#define W 512
#define NB 32
#define OUTW 56            // output columns per warp (lanes 0..27 x 2)
#define STRIPS 10          // 10*56 = 560 >= 512
#define YSEGS 16
#define YLEN 32
#define WARPS_TOTAL (STRIPS * NB * YSEGS)   // 5120
#define WPB 2
#define NBLOCKS (WARPS_TOTAL / WPB)         // 2560
#define RP 256             // float2 row pitch

__device__ float g_part[NBLOCKS];
__device__ int   g_cnt = 0;

// Pair-channel horizontal 9-window sums, INDEPENDENT-shfl form: all 5 shfls
// depend only on p/a0/a1, so they issue back-to-back (one latency exposure).
// hE[l] = sum local cols 2l..2l+8 ; hO[l] = sum local cols 2l+1..2l+9.
#define HSUM9I(a0, a1, hE, hO) do {                            \
    const float _p  = (a0) + (a1);                             \
    const float _p1 = __shfl_down_sync(0xffffffffu, _p, 1);    \
    const float _p2 = __shfl_down_sync(0xffffffffu, _p, 2);    \
    const float _p3 = __shfl_down_sync(0xffffffffu, _p, 3);    \
    const float _a4 = __shfl_down_sync(0xffffffffu, (a0), 4);  \
    const float _b4 = __shfl_down_sync(0xffffffffu, (a1), 4);  \
    (hE) = ((_p + _p1) + (_p2 + _p3)) + _a4;                   \
    (hO) = ((hE) - (a0)) + _b4;                                \
} while (0)

__global__ __launch_bounds__(64, 12) void cc_kernel(const float* __restrict__ inp,
                                                    const float* __restrict__ tgt,
                                                    float* __restrict__ out) {
    const int lane = threadIdx.x & 31;
    const int wid  = threadIdx.x >> 5;
    const int w    = blockIdx.x * WPB + wid;

    const int strip = w % STRIPS;
    const int rem   = w / STRIPS;          // 0..511
    const int b     = rem >> 4;            // 0..31
    const int y0    = (rem & 15) << 5;     // 0..480

    const int xs  = strip * OUTW;
    const int gx  = xs - 4 + 2 * lane;
    const bool cok = (unsigned)gx < W;
    const bool val = (lane < 28) && ((xs + 2 * lane) < W);

    const size_t boff = (size_t)b * (H * W) + (cok ? gx : 0);
    const float2* __restrict__ qI = (const float2*)(inp + boff) + (ptrdiff_t)(y0 - 4) * RP;
    const float2* __restrict__ qT = (const float2*)(tgt + boff) + (ptrdiff_t)(y0 - 4) * RP;
    int gyl = y0 - 4;      // next row index to LOAD (pointer-bumped)

    // vertical ring buffers of RAW rows: 4 values x 9 rows = 36 regs
    float ri0[9], ri1[9], rt0[9], rt1[9];
    #pragma unroll
    for (int k = 0; k < 9; k++) { ri0[k]=0.f; ri1[k]=0.f; rt0[k]=0.f; rt1[k]=0.f; }

    float VA0=0.f, VA1=0.f, VB0=0.f, VB1=0.f, VAA0=0.f, VAA1=0.f,
          VBB0=0.f, VBB1=0.f, VAB0=0.f, VAB1=0.f, acc=0.f;
    const float inv81 = 1.0f / 81.0f;

    // load the next sequential row, then bump
    #define LOADROW(I2v, T2v) do {                                 \
        I2v = make_float2(0.f, 0.f);                               \
        T2v = make_float2(0.f, 0.f);                               \
        if (cok && (unsigned)gyl < H) {                            \
            I2v = __ldg(qI);                                       \
            const float2 _t = __ldg(qT);                           \
            T2v.x = fmaf(_t.x, 0.5f, 0.5f);                        \
            T2v.y = fmaf(_t.y, 0.5f, 0.5f);                        \
        }                                                          \
        qI += RP; qT += RP; gyl++;                                 \
    } while (0)

    // sequential-channel emit; one fused reciprocal serves both columns.
    #define EMIT() do {                                                         \
        float SAE, SAO, SBE, SBO, SXE, SXO;                                     \
        HSUM9I(VA0, VA1, SAE, SAO);                                             \
        HSUM9I(VB0, VB1, SBE, SBO);                                             \
        const float tAE = SAE * inv81, tAO = SAO * inv81;                       \
        const float tBE = SBE * inv81, tBO = SBO * inv81;                       \
        HSUM9I(VAB0, VAB1, SXE, SXO);                                           \
        const float crE = fmaf(-tAE, SBE, SXE);                                 \
        const float crO = fmaf(-tAO, SBO, SXO);                                 \
        HSUM9I(VAA0, VAA1, SXE, SXO);                                           \
        const float ivE = fmaf(-tAE, SAE, SXE);                                 \
        const float ivO = fmaf(-tAO, SAO, SXO);                                 \
        HSUM9I(VBB0, VBB1, SXE, SXO);                                           \
        const float tvE = fmaf(-tBE, SBE, SXE);                                 \
        const float tvO = fmaf(-tBO, SBO, SXO);                                 \
        const float dE  = fmaf(tvE, ivE, 1e-5f);                                \
        const float dO  = fmaf(tvO, ivO, 1e-5f);                                \
        const float nE  = crE * crE;                                            \
        const float nO  = crO * crO;                                            \
        acc += __fdividef(fmaf(nE, dO, nO * dE), dE * dO);                      \
    } while (0)

    #define STEADY(kslot) do {                                                  \
        float2 nI, nT;                                                          \
        LOADROW(nI, nT);              /* prefetch next enter row */             \
        const float iv0 = cI.x, iv1 = cI.y, tv0 = cT.x, tv1 = cT.y;             \
        const float oi0 = ri0[kslot], oi1 = ri1[kslot];                         \
        const float ot0 = rt0[kslot], ot1 = rt1[kslot];                         \
        VA0 += iv0 - oi0;  VA1 += iv1 - oi1;                                    \
        VB0 += tv0 - ot0;  VB1 += tv1 - ot1;                                    \
        VAA0 = fmaf(-oi0, oi0, fmaf(iv0, iv0, VAA0));                           \
        VAA1 = fmaf(-oi1, oi1, fmaf(iv1, iv1, VAA1));                           \
        VBB0 = fmaf(-ot0, ot0, fmaf(tv0, tv0, VBB0));                           \
        VBB1 = fmaf(-ot1, ot1, fmaf(tv1, tv1, VBB1));                           \
        VAB0 = fmaf(-oi0, ot0, fmaf(iv0, tv0, VAB0));                           \
        VAB1 = fmaf(-oi1, ot1, fmaf(iv1, tv1, VAB1));                           \
        ri0[kslot] = iv0; ri1[kslot] = iv1; rt0[kslot] = tv0; rt1[kslot] = tv1; \
        cI = nI; cT = nT;                                                       \
        EMIT();                                                                 \
    } while (0)

    // prefetch first row (y0-4)
    float2 cI, cT;
    LOADROW(cI, cT);

    // ---- warmup: rows y0-4 .. y0+4 (slots 0..8), add-only; first output at end ----
    #pragma unroll
    for (int i = 0; i < 9; i++) {
        float2 nI, nT;
        LOADROW(nI, nT);
        const float iv0 = cI.x, iv1 = cI.y, tv0 = cT.x, tv1 = cT.y;
        VA0 += iv0;  VA1 += iv1;  VB0 += tv0;  VB1 += tv1;
        VAA0 = fmaf(iv0, iv0, VAA0);  VAA1 = fmaf(iv1, iv1, VAA1);
        VBB0 = fmaf(tv0, tv0, VBB0);  VBB1 = fmaf(tv1, tv1, VBB1);
        VAB0 = fmaf(iv0, tv0, VAB0);  VAB1 = fmaf(iv1, tv1, VAB1);
        ri0[i] = iv0; ri1[i] = iv1; rt0[i] = tv0; rt1[i] = tv1;
        cI = nI; cT = nT;
    }
    EMIT();   // output row y0

    // ---- steady: 31 more output rows = 3 full ring cycles + 4 tail ----
    #pragma unroll 1
    for (int j = 0; j < 3; j++) {
        #pragma unroll
        for (int k = 0; k < 9; k++) {
            STEADY(k);
        }
    }
    #pragma unroll
    for (int k = 0; k < 4; k++) {
        STEADY(k);
    }
    #undef LOADROW
    #undef EMIT
    #undef STEADY

    // mask invalid lanes once (their garbage is finite)
    acc = val ? acc : 0.f;

    // ---- reduction: warp -> block -> global partials -> last block finishes ----
    #pragma unroll
    for (int off = 16; off > 0; off >>= 1)
        acc += __shfl_down_sync(0xffffffffu, acc, off);

    __shared__ float sred[WPB];
    __shared__ int   slast;
    if (lane == 0) sred[wid] = acc;
    __syncthreads();
    if (threadIdx.x == 0) {
        g_part[blockIdx.x] = sred[0] + sred[1];
        __threadfence();
        int old = atomicAdd(&g_cnt, 1);
        slast = (old == NBLOCKS - 1) ? 1 : 0;
    }
    __syncthreads();

    if (slast) {
        // 2560 partials = 640 float4; 64 threads -> 10 float4 each
        double d = 0.0;
        const float4* p4 = (const float4*)g_part;
        #pragma unroll
        for (int r = 0; r < 10; r++) {
            const float4 v = p4[threadIdx.x + r * 64];
            d += (double)v.x + (double)v.y + (double)v.z + (double)v.w;
        }
        #pragma unroll
        for (int off = 16; off > 0; off >>= 1)
            d += __shfl_down_sync(0xffffffffu, d, off);
        __shared__ double dred[WPB];
        if (lane == 0) dred[wid] = d;
        __syncthreads();
        if (threadIdx.x == 0) {
            out[0] = (float)(-(dred[0] + dred[1]) / 8388608.0);   // 32*512*512
            g_cnt = 0;                            // reset for next graph replay
        }
    }
}

extern "C" void kernel_launch(void* const* d_in, const int* in_sizes, int n_in,
                              void* d_out, int out_size) {
    const float* inp = (const float*)d_in[0];
    const float* tgt = (const float*)d_in[1];
    // d_in[2] is the all-ones 9x9 filter; baked into the box sums.
    float* out = (float*)d_out;
    cc_kernel<<<NBLOCKS, 64>>>(inp, tgt, out);
}

// round 15
// speedup vs baseline: 1.0504x; 1.0504x over previous
#include <cuda_runtime.h>

#define H 512
#define W 512
#define NB 32
#define OUTW 112           // output columns per warp (lanes 0..27 x 4)
#define STRIPS 5           // 5*112 = 560 >= 512
#define YSEGS 16
#define YLEN 32
#define WARPS_TOTAL (STRIPS * NB * YSEGS)   // 2560
#define WPB 2
#define NBLOCKS (WARPS_TOTAL / WPB)         // 1280
#define RPF4 128           // float4 row pitch

__device__ float g_part[NBLOCKS];
__device__ int   g_cnt = 0;

// Quad horizontal 9-window sums: lane l holds local cols 4l..4l+3 in V[0..3].
// S[o] = 9-col window starting at local col 4l+o. 5 independent shfls.
#define HQUAD(V, S) do {                                        \
    const float _p2 = (V)[0] + (V)[1];                          \
    const float _p3 = _p2 + (V)[2];                             \
    const float _Q  = _p3 + (V)[3];                             \
    const float _Q1 = __shfl_down_sync(0xffffffffu, _Q, 1);     \
    const float _Q2 = __shfl_down_sync(0xffffffffu, _Q, 2);     \
    const float _v2 = __shfl_down_sync(0xffffffffu, (V)[0], 2); \
    const float _p22= __shfl_down_sync(0xffffffffu, _p2, 2);    \
    const float _p32= __shfl_down_sync(0xffffffffu, _p3, 2);    \
    (S)[0] = (_Q - 0.f)    + _Q1 + _v2;                         \
    (S)[1] = (_Q - (V)[0]) + _Q1 + _p22;                        \
    (S)[2] = ((V)[2]+(V)[3]) + _Q1 + _p32;                      \
    (S)[3] = (V)[3] + _Q1 + _Q2;                                \
} while (0)

__global__ __launch_bounds__(64, 12) void cc_kernel(const float* __restrict__ inp,
                                                    const float* __restrict__ tgt,
                                                    float* __restrict__ out) {
    const int lane = threadIdx.x & 31;
    const int wid  = threadIdx.x >> 5;
    const int w    = blockIdx.x * WPB + wid;

    const int strip = w % STRIPS;
    const int rem   = w / STRIPS;          // 0..511
    const int b     = rem >> 4;            // 0..31
    const int y0    = (rem & 15) << 5;     // 0..480

    const int xs   = strip * OUTW;
    const int gx   = xs - 4 + 4 * lane;    // first col of this lane's quad
    const bool cok = (unsigned)gx < W;
    const bool val = (lane < 28) && ((xs + 4 * lane) < W);

    const size_t boff = (size_t)b * (H * W) + (cok ? gx : 0);
    // pointer-bumped; q points at the NEXT row to load (enter side)
    const float4* __restrict__ qI = (const float4*)(inp + boff) + (ptrdiff_t)(y0 - 4) * RPF4;
    const float4* __restrict__ qT = (const float4*)(tgt + boff) + (ptrdiff_t)(y0 - 4) * RPF4;
    int gyl = y0 - 4;      // row index q currently points to

    float VA[4], VB[4], VAA[4], VBB[4], VAB[4];
    #pragma unroll
    for (int c = 0; c < 4; c++) { VA[c]=0.f; VB[c]=0.f; VAA[c]=0.f; VBB[c]=0.f; VAB[c]=0.f; }
    float acc = 0.f;
    const float inv81 = 1.0f / 81.0f;

    // load the row at the CURRENT pointer (row gyl), then bump
    #define LOADNEXT(I4, T4) do {                                  \
        I4[0]=0.f; I4[1]=0.f; I4[2]=0.f; I4[3]=0.f;                \
        T4[0]=0.f; T4[1]=0.f; T4[2]=0.f; T4[3]=0.f;                \
        if (cok && (unsigned)gyl < H) {                            \
            const float4 _i = __ldg(qI);                           \
            const float4 _t = __ldg(qT);                           \
            I4[0]=_i.x; I4[1]=_i.y; I4[2]=_i.z; I4[3]=_i.w;        \
            T4[0]=fmaf(_t.x,0.5f,0.5f); T4[1]=fmaf(_t.y,0.5f,0.5f);\
            T4[2]=fmaf(_t.z,0.5f,0.5f); T4[3]=fmaf(_t.w,0.5f,0.5f);\
        }                                                          \
        qI += RPF4; qT += RPF4; gyl++;                             \
    } while (0)

    // load the EXIT row: constant offset 10 rows behind the (pre-bump) pointer
    #define LOADEXIT(I4, T4) do {                                  \
        I4[0]=0.f; I4[1]=0.f; I4[2]=0.f; I4[3]=0.f;                \
        T4[0]=0.f; T4[1]=0.f; T4[2]=0.f; T4[3]=0.f;                \
        if (cok && (unsigned)(gyl - 10) < H) {                     \
            const float4 _i = __ldg(qI - 10 * RPF4);               \
            const float4 _t = __ldg(qT - 10 * RPF4);               \
            I4[0]=_i.x; I4[1]=_i.y; I4[2]=_i.z; I4[3]=_i.w;        \
            T4[0]=fmaf(_t.x,0.5f,0.5f); T4[1]=fmaf(_t.y,0.5f,0.5f);\
            T4[2]=fmaf(_t.z,0.5f,0.5f); T4[3]=fmaf(_t.w,0.5f,0.5f);\
        }                                                          \
    } while (0)

    // sequential-channel emit; pairwise-fused divisions (2 MUFU per 4 cols)
    #define EMIT() do {                                                         \
        float SA[4], SB[4], SX[4], tA[4], tB[4], cr[4];                         \
        HQUAD(VA, SA);                                                          \
        HQUAD(VB, SB);                                                          \
        _Pragma("unroll") for (int o = 0; o < 4; o++) {                         \
            tA[o] = SA[o] * inv81; tB[o] = SB[o] * inv81;                       \
        }                                                                       \
        HQUAD(VAB, SX);                                                         \
        _Pragma("unroll") for (int o = 0; o < 4; o++)                           \
            cr[o] = fmaf(-tA[o], SB[o], SX[o]);                                 \
        HQUAD(VAA, SX);                                                         \
        _Pragma("unroll") for (int o = 0; o < 4; o++)                           \
            tA[o] = fmaf(-tA[o], SA[o], SX[o]);      /* tA := ivar */           \
        HQUAD(VBB, SX);                                                         \
        _Pragma("unroll") for (int o = 0; o < 4; o++) {                         \
            tB[o] = fmaf(-tB[o], SB[o], SX[o]);      /* tB := tvar */           \
            tB[o] = fmaf(tB[o], tA[o], 1e-5f);       /* tB := den  */           \
            cr[o] = cr[o] * cr[o];                   /* cr := num  */           \
        }                                                                       \
        acc += __fdividef(fmaf(cr[0], tB[1], cr[1] * tB[0]), tB[0] * tB[1]);    \
        acc += __fdividef(fmaf(cr[2], tB[3], cr[3] * tB[2]), tB[2] * tB[3]);    \
    } while (0)

    // prefetch first row (y0-4)
    float cI[4], cT[4];
    LOADNEXT(cI, cT);

    // ---- warmup: rows y0-4 .. y0+4, add-only ----
    #pragma unroll
    for (int i = 0; i < 9; i++) {
        float nI[4], nT[4];
        LOADNEXT(nI, nT);
        #pragma unroll
        for (int c = 0; c < 4; c++) {
            VA[c] += cI[c];
            VB[c] += cT[c];
            VAA[c] = fmaf(cI[c], cI[c], VAA[c]);
            VBB[c] = fmaf(cT[c], cT[c], VBB[c]);
            VAB[c] = fmaf(cI[c], cT[c], VAB[c]);
            cI[c] = nI[c]; cT[c] = nT[c];
        }
    }
    EMIT();   // output row y0

    // ---- steady: 31 more output rows; enter prefetched, exit reloaded (L1) ----
    #pragma unroll 2
    for (int s = 0; s < 31; s++) {
        float nI[4], nT[4], xI[4], xT[4];
        LOADEXIT(xI, xT);           // row (enter-9), cache-resident
        LOADNEXT(nI, nT);           // prefetch next enter row
        #pragma unroll
        for (int c = 0; c < 4; c++) {
            VA[c] += cI[c] - xI[c];
            VB[c] += cT[c] - xT[c];
            VAA[c] = fmaf(-xI[c], xI[c], fmaf(cI[c], cI[c], VAA[c]));
            VBB[c] = fmaf(-xT[c], xT[c], fmaf(cT[c], cT[c], VBB[c]));
            VAB[c] = fmaf(-xI[c], xT[c], fmaf(cI[c], cT[c], VAB[c]));
            cI[c] = nI[c]; cT[c] = nT[c];
        }
        EMIT();
    }
    #undef LOADNEXT
    #undef LOADEXIT
    #undef EMIT

    // mask invalid lanes once (their garbage is finite)
    acc = val ? acc : 0.f;

    // ---- reduction: warp -> block -> global partials -> last block finishes ----
    #pragma unroll
    for (int off = 16; off > 0; off >>= 1)
        acc += __shfl_down_sync(0xffffffffu, acc, off);

    __shared__ float sred[WPB];
    __shared__ int   slast;
    if (lane == 0) sred[wid] = acc;
    __syncthreads();
    if (threadIdx.x == 0) {
        g_part[blockIdx.x] = sred[0] + sred[1];
        __threadfence();
        int old = atomicAdd(&g_cnt, 1);
        slast = (old == NBLOCKS - 1) ? 1 : 0;
    }
    __syncthreads();

    if (slast) {
        // 1280 partials = 320 float4; 64 threads -> 5 float4 each
        double d = 0.0;
        const float4* p4 = (const float4*)g_part;
        #pragma unroll
        for (int r = 0; r < 5; r++) {
            const float4 v = p4[threadIdx.x + r * 64];
            d += (double)v.x + (double)v.y + (double)v.z + (double)v.w;
        }
        #pragma unroll
        for (int off = 16; off > 0; off >>= 1)
            d += __shfl_down_sync(0xffffffffu, d, off);
        __shared__ double dred[WPB];
        if (lane == 0) dred[wid] = d;
        __syncthreads();
        if (threadIdx.x == 0) {
            out[0] = (float)(-(dred[0] + dred[1]) / 8388608.0);   // 32*512*512
            g_cnt = 0;                            // reset for next graph replay
        }
    }
}

extern "C" void kernel_launch(void* const* d_in, const int* in_sizes, int n_in,
                              void* d_out, int out_size) {
    const float* inp = (const float*)d_in[0];
    const float* tgt = (const float*)d_in[1];
    // d_in[2] is the all-ones 9x9 filter; baked into the box sums.
    float* out = (float*)d_out;
    cc_kernel<<<NBLOCKS, 64>>>(inp, tgt, out);
}

// round 16
// speedup vs baseline: 1.1121x; 1.0588x over previous
#include <cuda_runtime.h>

#define H 512
#define W 512
#define NB 32
#define OUTW 56            // output columns per warp (lanes 0..27 x 2)
#define STRIPS 10          // 10*56 = 560 >= 512
#define YSEGS 16
#define YLEN 32
#define WARPS_TOTAL (STRIPS * NB * YSEGS)   // 5120
#define WPB 2
#define NBLOCKS (WARPS_TOTAL / WPB)         // 2560
#define RP 256             // float2 row pitch

__device__ float g_part[NBLOCKS];
__device__ int   g_cnt = 0;

// Pair-channel horizontal 9-window sums. Lane l holds columns 2l (a0), 2l+1 (a1).
#define HSUM9P(a0, a1, hE, hO) do {                          \
    float _p  = (a0) + (a1);                                 \
    float _s  = _p + __shfl_down_sync(0xffffffffu, _p, 1);   \
    float _S4 = _s + __shfl_down_sync(0xffffffffu, _s, 2);   \
    (hE) = _S4  + __shfl_down_sync(0xffffffffu, (a0), 4);    \
    (hO) = (a1) + __shfl_down_sync(0xffffffffu, _S4, 1);     \
} while (0)

__global__ __launch_bounds__(64, 12) void cc_kernel(const float* __restrict__ inp,
                                                    const float* __restrict__ tgt,
                                                    float* __restrict__ out) {
    const int lane = threadIdx.x & 31;
    const int wid  = threadIdx.x >> 5;
    const int w    = blockIdx.x * WPB + wid;

    const int strip = w % STRIPS;
    const int rem   = w / STRIPS;          // 0..511
    const int b     = rem >> 4;            // 0..31
    const int y0    = (rem & 15) << 5;     // 0..480

    const int xs  = strip * OUTW;
    const int gx  = xs - 4 + 2 * lane;
    const bool cok = (unsigned)gx < W;
    const bool val = (lane < 28) && ((xs + 2 * lane) < W);

    const size_t boff = (size_t)b * (H * W) + (cok ? gx : 0);
    // pointer-bumped sequential row access (IADD instead of per-load IMAD)
    const float2* __restrict__ qI = (const float2*)(inp + boff) + (ptrdiff_t)(y0 - 4) * RP;
    const float2* __restrict__ qT = (const float2*)(tgt + boff) + (ptrdiff_t)(y0 - 4) * RP;
    int gyl = y0 - 4;      // row index qI/qT currently point to

    // vertical ring buffers of RAW rows: 4 values x 9 rows = 36 regs
    float ri0[9], ri1[9], rt0[9], rt1[9];
    #pragma unroll
    for (int k = 0; k < 9; k++) { ri0[k]=0.f; ri1[k]=0.f; rt0[k]=0.f; rt1[k]=0.f; }

    float VA0=0.f, VA1=0.f, VB0=0.f, VB1=0.f, VAA0=0.f, VAA1=0.f,
          VBB0=0.f, VBB1=0.f, VAB0=0.f, VAB1=0.f, acc=0.f;
    const float inv81 = 1.0f / 81.0f;

    // load the row at the current pointer, then bump
    #define LOADROW(I2v, T2v) do {                                 \
        I2v = make_float2(0.f, 0.f);                               \
        T2v = make_float2(0.f, 0.f);                               \
        if (cok && (unsigned)gyl < H) {                            \
            I2v = __ldg(qI);                                       \
            const float2 _t = __ldg(qT);                           \
            T2v.x = fmaf(_t.x, 0.5f, 0.5f);                        \
            T2v.y = fmaf(_t.y, 0.5f, 0.5f);                        \
        }                                                          \
        qI += RP; qT += RP; gyl++;                                 \
    } while (0)

    // sequential-channel emit; one fused reciprocal serves both columns.
    #define EMIT() do {                                                         \
        float SAE, SAO, SBE, SBO, SXE, SXO;                                     \
        HSUM9P(VA0, VA1, SAE, SAO);                                             \
        HSUM9P(VB0, VB1, SBE, SBO);                                             \
        const float tAE = SAE * inv81, tAO = SAO * inv81;                       \
        const float tBE = SBE * inv81, tBO = SBO * inv81;                       \
        HSUM9P(VAB0, VAB1, SXE, SXO);                                           \
        const float crE = fmaf(-tAE, SBE, SXE);                                 \
        const float crO = fmaf(-tAO, SBO, SXO);                                 \
        HSUM9P(VAA0, VAA1, SXE, SXO);                                           \
        const float ivE = fmaf(-tAE, SAE, SXE);                                 \
        const float ivO = fmaf(-tAO, SAO, SXO);                                 \
        HSUM9P(VBB0, VBB1, SXE, SXO);                                           \
        const float tvE = fmaf(-tBE, SBE, SXE);                                 \
        const float tvO = fmaf(-tBO, SBO, SXO);                                 \
        const float dE  = fmaf(tvE, ivE, 1e-5f);                                \
        const float dO  = fmaf(tvO, ivO, 1e-5f);                                \
        const float nE  = crE * crE;                                            \
        const float nO  = crO * crO;                                            \
        acc += __fdividef(fmaf(nE, dO, nO * dE), dE * dO);                      \
    } while (0)

    #define STEADY(kslot) do {                                                  \
        float2 nI, nT;                                                          \
        LOADROW(nI, nT);              /* prefetch next enter row */             \
        const float iv0 = cI.x, iv1 = cI.y, tv0 = cT.x, tv1 = cT.y;             \
        const float oi0 = ri0[kslot], oi1 = ri1[kslot];                         \
        const float ot0 = rt0[kslot], ot1 = rt1[kslot];                         \
        VA0 += iv0 - oi0;  VA1 += iv1 - oi1;                                    \
        VB0 += tv0 - ot0;  VB1 += tv1 - ot1;                                    \
        VAA0 = fmaf(-oi0, oi0, fmaf(iv0, iv0, VAA0));                           \
        VAA1 = fmaf(-oi1, oi1, fmaf(iv1, iv1, VAA1));                           \
        VBB0 = fmaf(-ot0, ot0, fmaf(tv0, tv0, VBB0));                           \
        VBB1 = fmaf(-ot1, ot1, fmaf(tv1, tv1, VBB1));                           \
        VAB0 = fmaf(-oi0, ot0, fmaf(iv0, tv0, VAB0));                           \
        VAB1 = fmaf(-oi1, ot1, fmaf(iv1, tv1, VAB1));                           \
        ri0[kslot] = iv0; ri1[kslot] = iv1; rt0[kslot] = tv0; rt1[kslot] = tv1; \
        cI = nI; cT = nT;                                                       \
        EMIT();                                                                 \
    } while (0)

    // prefetch first row (y0-4)
    float2 cI, cT;
    LOADROW(cI, cT);

    // ---- warmup: rows y0-4 .. y0+4 (slots 0..8), add-only; first output at end ----
    #pragma unroll
    for (int i = 0; i < 9; i++) {
        float2 nI, nT;
        LOADROW(nI, nT);
        const float iv0 = cI.x, iv1 = cI.y, tv0 = cT.x, tv1 = cT.y;
        VA0 += iv0;  VA1 += iv1;  VB0 += tv0;  VB1 += tv1;
        VAA0 = fmaf(iv0, iv0, VAA0);  VAA1 = fmaf(iv1, iv1, VAA1);
        VBB0 = fmaf(tv0, tv0, VBB0);  VBB1 = fmaf(tv1, tv1, VBB1);
        VAB0 = fmaf(iv0, tv0, VAB0);  VAB1 = fmaf(iv1, tv1, VAB1);
        ri0[i] = iv0; ri1[i] = iv1; rt0[i] = tv0; rt1[i] = tv1;
        cI = nI; cT = nT;
    }
    EMIT();   // output row y0

    // ---- steady: 31 more output rows = 3 full ring cycles + 4 tail ----
    #pragma unroll 1
    for (int j = 0; j < 3; j++) {
        #pragma unroll
        for (int k = 0; k < 9; k++) {
            STEADY(k);
        }
    }
    #pragma unroll
    for (int k = 0; k < 4; k++) {
        STEADY(k);
    }
    #undef LOADROW
    #undef EMIT
    #undef STEADY

    // mask invalid lanes once (their garbage is finite)
    acc = val ? acc : 0.f;

    // ---- reduction: warp -> block -> global partials -> last block finishes ----
    #pragma unroll
    for (int off = 16; off > 0; off >>= 1)
        acc += __shfl_down_sync(0xffffffffu, acc, off);

    __shared__ float sred[WPB];
    __shared__ int   slast;
    if (lane == 0) sred[wid] = acc;
    __syncthreads();
    if (threadIdx.x == 0) {
        g_part[blockIdx.x] = sred[0] + sred[1];
        __threadfence();
        int old = atomicAdd(&g_cnt, 1);
        slast = (old == NBLOCKS - 1) ? 1 : 0;
    }
    __syncthreads();

    if (slast) {
        // 2560 partials = 640 float4; 64 threads -> 10 float4 each
        double d = 0.0;
        const float4* p4 = (const float4*)g_part;
        #pragma unroll
        for (int r = 0; r < 10; r++) {
            const float4 v = p4[threadIdx.x + r * 64];
            d += (double)v.x + (double)v.y + (double)v.z + (double)v.w;
        }
        #pragma unroll
        for (int off = 16; off > 0; off >>= 1)
            d += __shfl_down_sync(0xffffffffu, d, off);
        __shared__ double dred[WPB];
        if (lane == 0) dred[wid] = d;
        __syncthreads();
        if (threadIdx.x == 0) {
            out[0] = (float)(-(dred[0] + dred[1]) / 8388608.0);   // 32*512*512
            g_cnt = 0;                            // reset for next graph replay
        }
    }
}

extern "C" void kernel_launch(void* const* d_in, const int* in_sizes, int n_in,
                              void* d_out, int out_size) {
    const float* inp = (const float*)d_in[0];
    const float* tgt = (const float*)d_in[1];
    // d_in[2] is the all-ones 9x9 filter; baked into the box sums.
    float* out = (float*)d_out;
    cc_kernel<<<NBLOCKS, 64>>>(inp, tgt, out);
}